// round 7
// baseline (speedup 1.0000x reference)
#include <cuda_runtime.h>
#include <math.h>

#define BB    1024
#define SS    277
#define RR    76
#define ZZ    56
#define NLHSC 24
#define NROWS (BB * SS)          // 283648 = 1108 * 256 = 8864 warps * 32 rows
#define BCEB  1108
#define ILP   80                 // padded index-list stride

__device__ double   g_bce_acc = 0.0;
__device__ float    g_var[ZZ * ZZ];   // zero-initialized
__device__ float    g_avg[ZZ];        // zero-initialized
__device__ unsigned g_done = 0;

// mask structure, rebuilt by mom_k every launch (deterministic)
__device__ int           g_cnt[NLHSC];
__device__ unsigned char g_idx[NLHSC * ILP];  // unmasked indices, 0xFF padded
__device__ unsigned char g_bit[NLHSC * RR];
__device__ unsigned char g_lhs[RR];

__device__ __forceinline__ float fast_tanh(float x) {
    float y;
    asm("tanh.approx.f32 %0, %1;" : "=f"(y) : "f"(x));
    return y;
}

// ---------------------------------------------------------------------------
// mom_k: 16 blocks. Gram of mu (56x56) via register-tiled 4x4 outer products
// + column sums (float atomics). Block 0 also builds the per-LHS
// unmasked-index lists used by bce_k.
// ---------------------------------------------------------------------------
#define MOMB  16
#define MROWS (BB / MOMB)
__global__ void __launch_bounds__(256) mom_k(
    const float* __restrict__ mu,
    const float* __restrict__ masks,
    const int*   __restrict__ ind2lhs)
{
    __shared__ float s[MROWS * ZZ];
    const float* src = mu + (size_t)blockIdx.x * MROWS * ZZ;
    for (int i = threadIdx.x; i < MROWS * ZZ / 4; i += 256)
        ((float4*)s)[i] = ((const float4*)src)[i];
    __syncthreads();

    const int t = threadIdx.x;

    if (blockIdx.x == 0) {
        if (t < RR) g_lhs[t] = (unsigned char)ind2lhs[t];
        if (t >= 196 && t < 196 + NLHSC) {
            const int l = t - 196;
            int c = 0;
            for (int r = 0; r < RR; r++) {
                const int b = (masks[l * RR + r] > 0.f);
                g_bit[l * RR + r] = (unsigned char)b;
                if (b) g_idx[l * ILP + c++] = (unsigned char)r;
            }
            g_cnt[l] = c;
            for (; c < ILP; c++) g_idx[l * ILP + c] = 0xFF;
        }
    }

    if (t < 196) {
        const int i0 = (t % 14) * 4;
        const int j0 = (t / 14) * 4;
        float a[4][4] = {};
        float rs[4]   = {};
        for (int b = 0; b < MROWS; b++) {
            float4 av = *(const float4*)&s[b * ZZ + i0];
            float4 bv = *(const float4*)&s[b * ZZ + j0];
            float A[4]  = {av.x, av.y, av.z, av.w};
            float Bv[4] = {bv.x, bv.y, bv.z, bv.w};
            #pragma unroll
            for (int p = 0; p < 4; p++)
                #pragma unroll
                for (int q = 0; q < 4; q++)
                    a[p][q] += A[p] * Bv[q];
            if (j0 == 0) {
                #pragma unroll
                for (int p = 0; p < 4; p++) rs[p] += A[p];
            }
        }
        #pragma unroll
        for (int p = 0; p < 4; p++)
            #pragma unroll
            for (int q = 0; q < 4; q++)
                atomicAdd(&g_var[(i0 + p) * ZZ + j0 + q], a[p][q]);
        if (j0 == 0) {
            #pragma unroll
            for (int p = 0; p < 4; p++) atomicAdd(&g_avg[i0 + p], rs[p]);
        }
    }
}

// ---------------------------------------------------------------------------
// bce_k: warp-per-row, coalesced loads, register-shuffle sparse gather.
// Row's 76 x-values live in 3 regs/lane (coalesced LDG, prefetched one row
// ahead). Sparse unmasked element k is fetched lane-locally with 3 shuffles
// + selects — zero gather memory traffic. Masked entries are excluded from
// the softmax (exact in f32 vs the reference's shift_to_tiny: masked probs
// <= 3.7e-44 vanish; masked target clamps to exactly -100). No
// max-subtraction: |x| <= ~5.7 for N(0,1) inputs, exp cannot overflow.
// ---------------------------------------------------------------------------
__global__ void __launch_bounds__(256) bce_k(
    const float* __restrict__ x_all,
    const float* __restrict__ t_all,
    float*       __restrict__ out)
{
    __shared__ unsigned char s_idx[NLHSC * ILP];
    __shared__ unsigned char s_bit[NLHSC * RR];
    __shared__ unsigned char s_lhs[RR];
    __shared__ int           s_cnt[NLHSC];
    __shared__ double        sredd[256];
    __shared__ unsigned      sticket;

    const int tid = threadIdx.x;
    for (int i = tid; i < NLHSC * ILP; i += 256) s_idx[i] = g_idx[i];
    for (int i = tid; i < NLHSC * RR;  i += 256) s_bit[i] = g_bit[i];
    if (tid < RR)    s_lhs[tid] = g_lhs[tid];
    if (tid < NLHSC) s_cnt[tid] = g_cnt[tid];
    __syncthreads();

    const int lane = tid & 31;
    const int gw   = blockIdx.x * 8 + (tid >> 5);
    const int nw   = gridDim.x * 8;
    const bool v2  = lane < (RR - 64);   // lanes 0..11

    double acc = 0.0;
    int row = gw;

    // prefetch first row
    float cx0, cx1, cx2, ct0, ct1, ct2;
    {
        const float* x = x_all + (size_t)row * RR;
        const float* t = t_all + (size_t)row * RR;
        cx0 = __ldcs(x + lane); cx1 = __ldcs(x + lane + 32);
        cx2 = v2 ? __ldcs(x + lane + 64) : 0.f;
        ct0 = __ldcs(t + lane); ct1 = __ldcs(t + lane + 32);
        ct2 = v2 ? __ldcs(t + lane + 64) : 0.f;
    }

    for (; row < NROWS; row += nw) {
        const int nr = row + nw;
        float nx0 = 0.f, nx1 = 0.f, nx2 = 0.f, nt0 = 0.f, nt1 = 0.f, nt2 = 0.f;
        if (nr < NROWS) {
            const float* x = x_all + (size_t)nr * RR;
            const float* t = t_all + (size_t)nr * RR;
            nx0 = __ldcs(x + lane); nx1 = __ldcs(x + lane + 32);
            nx2 = v2 ? __ldcs(x + lane + 64) : 0.f;
            nt0 = __ldcs(t + lane); nt1 = __ldcs(t + lane + 32);
            nt2 = v2 ? __ldcs(t + lane + 64) : 0.f;
        }

        // ---- argmax of one-hot target: 3 ballots + ffs ----
        const unsigned b0 = __ballot_sync(0xFFFFFFFFu, ct0 > 0.5f);
        const unsigned b1 = __ballot_sync(0xFFFFFFFFu, ct1 > 0.5f);
        const unsigned b2 = __ballot_sync(0xFFFFFFFFu, ct2 > 0.5f);
        const int tr = b0 ? (__ffs(b0) - 1)
                          : (b1 ? (__ffs(b1) + 31) : (__ffs(b2) + 63));

        const int lhs = s_lhs[tr];
        const int cnt = s_cnt[lhs];
        const unsigned char* il = s_idx + lhs * ILP;

        // ---- group A: element il[lane] via register shuffle gather ----
        const int ia = il[lane];
        float ga0 = __shfl_sync(0xFFFFFFFFu, cx0, ia & 31);
        float ga1 = __shfl_sync(0xFFFFFFFFu, cx1, ia & 31);
        float ga2 = __shfl_sync(0xFFFFFFFFu, cx2, ia & 31);
        const float xa = (ia < 32) ? ga0 : ((ia < 64) ? ga1 : ga2);
        const float ea = (ia < RR) ? __expf(xa) : 0.f;

        // ---- rare spill groups (warp-uniform branches) ----
        float eb = 0.f, xb = 0.f; int ib = 0xFF;
        float ec = 0.f, xc = 0.f; int ic = 0xFF;
        if (cnt > 32) {
            ib = il[lane + 32];
            float g0 = __shfl_sync(0xFFFFFFFFu, cx0, ib & 31);
            float g1 = __shfl_sync(0xFFFFFFFFu, cx1, ib & 31);
            float g2 = __shfl_sync(0xFFFFFFFFu, cx2, ib & 31);
            xb = (ib < 32) ? g0 : ((ib < 64) ? g1 : g2);
            eb = (ib < RR) ? __expf(xb) : 0.f;
            if (cnt > 64) {
                ic = il[lane + 64];
                float h0 = __shfl_sync(0xFFFFFFFFu, cx0, ic & 31);
                float h1 = __shfl_sync(0xFFFFFFFFu, cx1, ic & 31);
                float h2 = __shfl_sync(0xFFFFFFFFu, cx2, ic & 31);
                xc = (ic < 32) ? h0 : ((ic < 64) ? h1 : h2);
                ec = (ic < RR) ? __expf(xc) : 0.f;
            }
        }

        // ---- denominator: warp sum ----
        float den = ea + eb + ec;
        #pragma unroll
        for (int o = 16; o; o >>= 1)
            den += __shfl_xor_sync(0xFFFFFFFFu, den, o);
        const float logden = __logf(den);

        // ---- terms (inactive lanes give exactly log(den)-logden = 0) ----
        float s = (ia == tr) ? fmaxf(xa - logden, -100.f)
                             : fmaxf(__logf(den - ea) - logden, -100.f);
        if (cnt > 32) {
            s += (ib == tr) ? fmaxf(xb - logden, -100.f)
                            : fmaxf(__logf(den - eb) - logden, -100.f);
            if (cnt > 64)
                s += (ic == tr) ? fmaxf(xc - logden, -100.f)
                                : fmaxf(__logf(den - ec) - logden, -100.f);
        }
        // masked target contributes exactly -100 (one lane adds it)
        if (lane == 0 && !s_bit[lhs * RR + tr]) s -= 100.f;

        acc += (double)s;

        cx0 = nx0; cx1 = nx1; cx2 = nx2;
        ct0 = nt0; ct1 = nt1; ct2 = nt2;
    }

    // block reduce (double) + one atomic
    sredd[tid] = acc;
    __syncthreads();
    for (int s = 128; s > 0; s >>= 1) {
        if (tid < s) sredd[tid] += sredd[tid + s];
        __syncthreads();
    }
    if (tid == 0) {
        atomicAdd(&g_bce_acc, sredd[0]);
        __threadfence();
        sticket = atomicAdd(&g_done, 1u);
    }
    __syncthreads();

    // last block finalizes moment terms (mom_k ran as the previous kernel)
    if (sticket == gridDim.x - 1) {
        float local = 0.f;
        for (int p = tid; p < ZZ * ZZ; p += 256) {
            const int i = p / ZZ, j = p - i * ZZ;
            float v = ((volatile float*)g_var)[p] * (1.0f / (float)BB)
                      - ((i == j) ? 1.0f : 0.0f);
            local += fast_tanh(v) * v;
            ((volatile float*)g_var)[p] = 0.f;   // reset for next replay
        }
        float la = 0.f;
        if (tid < ZZ) {
            float am = ((volatile float*)g_avg)[tid] * (1.0f / (float)BB);
            la = am * am;
            ((volatile float*)g_avg)[tid] = 0.f;
        }
        sredd[tid] = (double)local / ((double)ZZ * (double)ZZ)
                   + (double)la / (double)ZZ;
        __syncthreads();
        for (int s = 128; s > 0; s >>= 1) {
            if (tid < s) sredd[tid] += sredd[tid + s];
            __syncthreads();
        }
        if (tid == 0) {
            double bsum = *((volatile double*)&g_bce_acc);
            out[0] = (float)(-bsum / ((double)BB * (double)RR) + sredd[0]);
            *((volatile double*)&g_bce_acc) = 0.0;
            g_done = 0;
        }
    }
}

extern "C" void kernel_launch(void* const* d_in, const int* in_sizes, int n_in,
                              void* d_out, int out_size)
{
    (void)in_sizes; (void)n_in; (void)out_size;
    const float* model_out_x = (const float*)d_in[0];
    const float* mu          = (const float*)d_in[1];
    // d_in[2] = log_var (unused: sample_z=False, training mode)
    const float* target_x    = (const float*)d_in[3];
    const float* masks       = (const float*)d_in[4];
    const int*   ind2lhs     = (const int*)d_in[5];
    float* out = (float*)d_out;

    mom_k<<<MOMB, 256>>>(mu, masks, ind2lhs);
    bce_k<<<BCEB, 256>>>(model_out_x, target_x, out);
}

// round 8
// speedup vs baseline: 1.5559x; 1.5559x over previous
#include <cuda_runtime.h>
#include <math.h>

#define BB    1024
#define SS    277
#define RR    76
#define ZZ    56
#define NLHSC 24
#define NROWS (BB * SS)           // 283648 = 64 * 4432
#define TROWS 64                  // rows per block tile
#define NT4   (TROWS * RR / 4)    // 1216 float4 per tile
#define BCEB  (NROWS / TROWS)     // 4432 blocks

__device__ double   g_bce_acc = 0.0;
__device__ float    g_var[ZZ * ZZ];   // zero-initialized
__device__ float    g_avg[ZZ];        // zero-initialized
__device__ unsigned g_done = 0;

__device__ __forceinline__ float fast_tanh(float x) {
    float y;
    asm("tanh.approx.f32 %0, %1;" : "=f"(y) : "f"(x));
    return y;
}
__device__ __forceinline__ void cp_async16(void* sdst, const void* gsrc) {
    unsigned sa = (unsigned)__cvta_generic_to_shared(sdst);
    asm volatile("cp.async.cg.shared.global [%0], [%1], 16;" :: "r"(sa), "l"(gsrc));
}
#define CP_COMMIT() asm volatile("cp.async.commit_group;")
#define CP_WAIT0()  asm volatile("cp.async.wait_group 0;" ::: "memory")

// ---------------------------------------------------------------------------
// mom_k: 16 blocks. Gram of mu (56x56) via register-tiled 4x4 outer products
// + column sums, float atomics into g_var/g_avg.
// ---------------------------------------------------------------------------
#define MOMB  16
#define MROWS (BB / MOMB)
__global__ void __launch_bounds__(256) mom_k(const float* __restrict__ mu)
{
    __shared__ float s[MROWS * ZZ];
    const float* src = mu + (size_t)blockIdx.x * MROWS * ZZ;
    for (int i = threadIdx.x; i < MROWS * ZZ / 4; i += 256)
        ((float4*)s)[i] = ((const float4*)src)[i];
    __syncthreads();

    const int t = threadIdx.x;
    if (t < 196) {
        const int i0 = (t % 14) * 4;
        const int j0 = (t / 14) * 4;
        float a[4][4] = {};
        float rs[4]   = {};
        for (int b = 0; b < MROWS; b++) {
            float4 av = *(const float4*)&s[b * ZZ + i0];
            float4 bv = *(const float4*)&s[b * ZZ + j0];
            float A[4]  = {av.x, av.y, av.z, av.w};
            float Bv[4] = {bv.x, bv.y, bv.z, bv.w};
            #pragma unroll
            for (int p = 0; p < 4; p++)
                #pragma unroll
                for (int q = 0; q < 4; q++)
                    a[p][q] += A[p] * Bv[q];
            if (j0 == 0) {
                #pragma unroll
                for (int p = 0; p < 4; p++) rs[p] += A[p];
            }
        }
        #pragma unroll
        for (int p = 0; p < 4; p++)
            #pragma unroll
            for (int q = 0; q < 4; q++)
                atomicAdd(&g_var[(i0 + p) * ZZ + j0 + q], a[p][q]);
        if (j0 == 0) {
            #pragma unroll
            for (int p = 0; p < 4; p++) atomicAdd(&g_avg[i0 + p], rs[p]);
        }
    }
}

// ---------------------------------------------------------------------------
// bce_k: 64-row tile staged to smem via cp.async (coalesced, no register
// transit); t scanned in flight for the one-hot index. Compute: 8 lanes per
// row (4 rows per warp instruction), conflict-free scalar LDS, den via 3
// bfly shuffles. Dense element loop: masked entries contribute exactly
// log(den)-log(den) = 0 (identical in f32 to the reference's shift_to_tiny;
// masked target clamps to exactly -100 via log(0) -> clamp). No max
// subtraction: |x| <= ~5.7 for N(0,1) inputs, exp cannot overflow.
// Last block (done-ticket) finalizes the moment terms and resets state.
// ---------------------------------------------------------------------------
__global__ void __launch_bounds__(256) bce_k(
    const float* __restrict__ x_all,
    const float* __restrict__ t_all,
    const float* __restrict__ masks,
    const int*   __restrict__ ind2lhs,
    float*       __restrict__ out)
{
    __shared__ float         s_x[TROWS * RR];    // 19456 B
    __shared__ float         s_m[NLHSC * RR];    //  7296 B
    __shared__ int           s_tr[TROWS];        //   256 B
    __shared__ unsigned char s_lhs[80];
    __shared__ float         sred[256];
    __shared__ unsigned      sticket;

    const int tid = threadIdx.x;
    const float4* x4 = (const float4*)x_all + (size_t)blockIdx.x * NT4;
    const float4* t4 = (const float4*)t_all + (size_t)blockIdx.x * NT4;

    // stage x tile (async, bypass L1)
    float4* sx4 = (float4*)s_x;
    #pragma unroll
    for (int i = tid; i < NT4; i += 256)
        cp_async16(&sx4[i], &x4[i]);
    CP_COMMIT();

    // masks + lhs map (L2-cached after first blocks)
    float4* sm4 = (float4*)s_m;
    for (int i = tid; i < NLHSC * RR / 4; i += 256)
        sm4[i] = ((const float4*)masks)[i];
    if (tid < RR) s_lhs[tid] = (unsigned char)ind2lhs[tid];

    // scan t tile for one-hot indices (each row has exactly one 1.0)
    #pragma unroll
    for (int i = tid; i < NT4; i += 256) {
        float4 v = t4[i];
        const int row = i / 19;
        const int pos = (i - row * 19) * 4;
        if (v.x > 0.5f) s_tr[row] = pos;
        if (v.y > 0.5f) s_tr[row] = pos + 1;
        if (v.z > 0.5f) s_tr[row] = pos + 2;
        if (v.w > 0.5f) s_tr[row] = pos + 3;
    }

    CP_WAIT0();
    __syncthreads();

    // ---- compute: 8 lanes per row, 4 rows per warp, 2 iterations ----
    const int w    = tid >> 5;
    const int lane = tid & 31;
    const int sub  = lane >> 3;   // row within 4-row group
    const int k    = lane & 7;    // element phase

    float acc = 0.f;
    #pragma unroll
    for (int it = 0; it < 2; it++) {
        const int rl  = w * 8 + it * 4 + sub;     // local row 0..63
        const int tr  = s_tr[rl];
        const int lhs = s_lhs[tr];
        const float* xr = s_x + rl * RR;
        const float* mr = s_m + lhs * RR;

        float e[10];
        float den = 0.f;
        #pragma unroll
        for (int j = 0; j < 9; j++) {
            const int el = k + 8 * j;
            e[j] = mr[el] * __expf(xr[el]);
            den += e[j];
        }
        {   // tail: elements 72..75 live on lanes k<4
            const int el = k + 72;
            e[9] = (el < RR) ? mr[el] * __expf(xr[el]) : 0.f;
            den += e[9];
        }
        den += __shfl_xor_sync(0xFFFFFFFFu, den, 1);
        den += __shfl_xor_sync(0xFFFFFFFFu, den, 2);
        den += __shfl_xor_sync(0xFFFFFFFFu, den, 4);
        const float logden = __logf(den);

        float s = 0.f;
        #pragma unroll
        for (int j = 0; j < 10; j++)
            s += fmaxf(__logf(den - e[j]) - logden, -100.f);
        // masked entries: e=0 -> log(den)-logden = 0 exactly.
        // invalid tail lanes: e[9]=0 -> 0.

        // target fixup on the owning lane (k == tr mod 8)
        if (k == (tr & 7)) {
            const float xtr = xr[tr];
            const float mtr = mr[tr];
            const float etr = mtr * __expf(xtr);
            const float wrong = fmaxf(__logf(den - etr) - logden, -100.f);
            const float rarg  = (mtr > 0.f) ? etr : 0.f;   // log(0)->-inf->-100
            const float right = fmaxf(__logf(rarg) - logden, -100.f);
            s += right - wrong;
        }
        acc += s;
    }

    // block reduce + one atomic
    sred[tid] = acc;
    __syncthreads();
    for (int s = 128; s > 0; s >>= 1) {
        if (tid < s) sred[tid] += sred[tid + s];
        __syncthreads();
    }
    if (tid == 0) {
        atomicAdd(&g_bce_acc, (double)sred[0]);
        __threadfence();
        sticket = atomicAdd(&g_done, 1u);
    }
    __syncthreads();

    // last block finalizes moment terms (mom_k ran as the previous kernel)
    if (sticket == gridDim.x - 1) {
        float local = 0.f;
        for (int p = tid; p < ZZ * ZZ; p += 256) {
            const int i = p / ZZ, j = p - i * ZZ;
            float v = ((volatile float*)g_var)[p] * (1.0f / (float)BB)
                      - ((i == j) ? 1.0f : 0.0f);
            local += fast_tanh(v) * v;
            ((volatile float*)g_var)[p] = 0.f;   // reset for next replay
        }
        float la = 0.f;
        if (tid < ZZ) {
            float am = ((volatile float*)g_avg)[tid] * (1.0f / (float)BB);
            la = am * am;
            ((volatile float*)g_avg)[tid] = 0.f;
        }
        double term = (double)local / ((double)ZZ * (double)ZZ)
                    + (double)la / (double)ZZ;
        // reuse sred as double via separate shared? keep double precision:
        __shared__ double sredd[256];
        sredd[tid] = term;
        __syncthreads();
        for (int s = 128; s > 0; s >>= 1) {
            if (tid < s) sredd[tid] += sredd[tid + s];
            __syncthreads();
        }
        if (tid == 0) {
            double bsum = *((volatile double*)&g_bce_acc);
            out[0] = (float)(-bsum / ((double)BB * (double)RR) + sredd[0]);
            *((volatile double*)&g_bce_acc) = 0.0;
            g_done = 0;
        }
    }
}

extern "C" void kernel_launch(void* const* d_in, const int* in_sizes, int n_in,
                              void* d_out, int out_size)
{
    (void)in_sizes; (void)n_in; (void)out_size;
    const float* model_out_x = (const float*)d_in[0];
    const float* mu          = (const float*)d_in[1];
    // d_in[2] = log_var (unused: sample_z=False, training mode)
    const float* target_x    = (const float*)d_in[3];
    const float* masks       = (const float*)d_in[4];
    const int*   ind2lhs     = (const int*)d_in[5];
    float* out = (float*)d_out;

    mom_k<<<MOMB, 256>>>(mu);
    bce_k<<<BCEB, 256>>>(model_out_x, target_x, masks, ind2lhs, out);
}